// round 16
// baseline (speedup 1.0000x reference)
#include <cuda_runtime.h>
#include <cuda_fp16.h>
#include <math.h>
#include <stdint.h>

// ---------------- problem dims ----------------
#define DFEAT 256
#define KDIM  512
#define H     128
#define H2    64
#define NC1   192          // fused stage-1 output cols (W1 | Ws)
#define MTILE 128          // edges per CTA
#define KC    64           // K-chunk
#define THREADS 512        // 16 warps: 4 m-warps x 4 n-warps

// ---------------- smem layout (bytes) ----------------
#define OFF_PS   0          // [128][4] float row partial sums
#define OFF_PQ   2048
#define OFF_MU   4096
#define OFF_RS   4608
#define OFF_RIDX 5120       // int[256]
// double-buffered stage-1 chunk sets (row pitch 144B = 64 fp16 + 16B pad)
#define CHUNK0   6144
#define A1HI_R   0          // 128*144 = 18432
#define A1LO_R   18432
#define B1_R     36864      // 192*144 = 27648
#define CHUNKSZ  64512
// phase 2 (aliases chunk buffers; pitch 272B = 128 fp16 + 16B pad)
#define OFF_A2HI 6144       // 128*272 = 34816
#define OFF_A2LO 40960
#define OFF_B2HI 75776      // 64*272 = 17408
#define OFF_B2LO 93184
#define OFF_ID   110592     // [128][64] float identity (ends 143360)
#define SMEM_BYTES 143360

// ---------------- prepped weights ----------------
__device__ __align__(16) __half g_WcatT[NC1 * KDIM];   // [n][k] fp16 (single)
__device__ __align__(16) __half g_W2T_hi[H2 * H];      // [n][k]
__device__ __align__(16) __half g_W2T_lo[H2 * H];

// ---------------- helpers ----------------
__device__ __forceinline__ uint32_t smem_u32(const void* p) {
    uint32_t a;
    asm("{ .reg .u64 t; cvta.to.shared.u64 t, %1; cvt.u32.u64 %0, t; }" : "=r"(a) : "l"(p));
    return a;
}
__device__ __forceinline__ void ldsm_x4(uint32_t addr, uint32_t* r) {
    asm volatile("ldmatrix.sync.aligned.m8n8.x4.shared.b16 {%0,%1,%2,%3}, [%4];"
        : "=r"(r[0]), "=r"(r[1]), "=r"(r[2]), "=r"(r[3]) : "r"(addr));
}
__device__ __forceinline__ void mma_f16(float* d, const uint32_t* a, const uint32_t* b) {
    asm volatile(
        "mma.sync.aligned.m16n8k16.row.col.f32.f16.f16.f32 "
        "{%0,%1,%2,%3}, {%4,%5,%6,%7}, {%8,%9}, {%0,%1,%2,%3};"
        : "+f"(d[0]), "+f"(d[1]), "+f"(d[2]), "+f"(d[3])
        : "r"(a[0]), "r"(a[1]), "r"(a[2]), "r"(a[3]), "r"(b[0]), "r"(b[1]));
}
__device__ __forceinline__ uint32_t pack_h(__half a, __half b) {
    return (uint32_t)__half_as_ushort(a) | ((uint32_t)__half_as_ushort(b) << 16);
}
__device__ __forceinline__ void split2h(float f, __half& h, __half& l) {
    h = __float2half_rn(f);
    l = __float2half_rn(f - __half2float(h));
}
__device__ __forceinline__ float gelu_exact(float x) {
    return 0.5f * x * (1.0f + erff(x * 0.70710678118654752440f));
}

// ---------------- prep kernel: convert/split + transpose weights ----------------
__global__ void prep_weights(const float* __restrict__ W1, const float* __restrict__ Ws,
                             const float* __restrict__ W2) {
    int i = blockIdx.x * 256 + threadIdx.x;
    if (i < NC1 * KDIM) {
        int n = i / KDIM, k = i % KDIM;
        float w = (n < H) ? W1[k * H + n] : Ws[k * H2 + (n - H)];
        g_WcatT[i] = __float2half_rn(w);
    } else {
        int j = i - NC1 * KDIM;
        if (j < H2 * H) {
            int n = j / H, k = j % H;
            float w = W2[k * H2 + n];
            __half h, l; split2h(w, h, l);
            g_W2T_hi[j] = h; g_W2T_lo[j] = l;
        }
    }
}

// ---------------- main kernel ----------------
__global__ void __launch_bounds__(THREADS, 1)
mlp_hmma_kernel(const float* __restrict__ drug, const float* __restrict__ dis,
                const int* __restrict__ src, const int* __restrict__ dst,
                const float* __restrict__ b1, const float* __restrict__ g1,
                const float* __restrict__ be1,
                const float* __restrict__ b2, const float* __restrict__ g2,
                const float* __restrict__ be2,
                const float* __restrict__ W3, const float* __restrict__ b3,
                const float* __restrict__ bs,
                float* __restrict__ out, int E)
{
    extern __shared__ char smem[];
    const uint32_t sb = smem_u32(smem);
    const int tid = threadIdx.x, wid = tid >> 5, lane = tid & 31;
    const int e0 = blockIdx.x * MTILE;

    float* psum = (float*)(smem + OFF_PS);
    float* psq  = (float*)(smem + OFF_PQ);
    float* mu_s = (float*)(smem + OFF_MU);
    float* rs_s = (float*)(smem + OFF_RS);
    int*   ridx = (int*)(smem + OFF_RIDX);
    float* idbf = (float*)(smem + OFF_ID);

    if (tid < MTILE) {
        int e = e0 + tid;
        ridx[tid]         = (e < E) ? src[e] : 0;
        ridx[MTILE + tid] = (e < E) ? dst[e] : 0;
    }
    __syncthreads();

    // warp tiling
    const int mw = wid >> 2, nw = wid & 3;
    const int m0 = mw * 32;
    const int n0 = nw * 48;
    const int lrow = lane & 15;
    const int kcol = (lane >> 4) * 8;
    const int brow = (lane & 7) + ((lane >> 4) * 8);
    const int bcol = ((lane >> 3) & 1) * 8;
    const int qr = lane >> 2;
    const int qc = (lane & 3) * 2;

    const uint32_t aoffA = (m0 + lrow) * 144 + kcol * 2;
    const uint32_t boffB = (n0 + brow) * 144 + bcol * 2;

    // staging coords
    const int grow = tid >> 2, gq = tid & 3;   // A gather: 128 rows x 4 thr

    float acc[2][6][4];
    #pragma unroll
    for (int mi = 0; mi < 2; ++mi)
        #pragma unroll
        for (int ni = 0; ni < 6; ++ni)
            #pragma unroll
            for (int j = 0; j < 4; ++j) acc[mi][ni][j] = 0.0f;

    float4 aReg[4];
    uint4  bReg[3];

    // ---- prefetch helpers ----
    auto load_chunk = [&](int cc) {
        const float* tab = (cc < 4) ? drug : dis;
        const long idx = (long)ridx[((cc < 4) ? 0 : MTILE) + grow];
        const float* sp = tab + idx * DFEAT + (cc & 3) * KC + gq * 16;
        #pragma unroll
        for (int j = 0; j < 4; ++j) aReg[j] = *(const float4*)(sp + 4 * j);
        // B tile: 192 rows x 8 uint4 slots = 1536 slots = exactly 3 iterations
        #pragma unroll
        for (int it = 0; it < 3; ++it) {
            int s = tid + it * THREADS;        // 0..1535
            int n = s >> 3, j = s & 7;
            bReg[it] = *(const uint4*)((const char*)g_WcatT + n * 1024 + cc * 128 + j * 16);
        }
    };
    auto store_chunk = [&](int bsel) {
        char* base = smem + CHUNK0 + bsel * CHUNKSZ;
        char* dh = base + A1HI_R + grow * 144 + gq * 32;
        char* dl = base + A1LO_R + grow * 144 + gq * 32;
        #pragma unroll
        for (int j = 0; j < 4; ++j) {
            __half h0,h1,h2,h3,l0,l1,l2,l3;
            split2h(aReg[j].x, h0, l0); split2h(aReg[j].y, h1, l1);
            split2h(aReg[j].z, h2, l2); split2h(aReg[j].w, h3, l3);
            *(uint2*)(dh + j * 8) = make_uint2(pack_h(h0,h1), pack_h(h2,h3));
            *(uint2*)(dl + j * 8) = make_uint2(pack_h(l0,l1), pack_h(l2,l3));
        }
        #pragma unroll
        for (int it = 0; it < 3; ++it) {
            int s = tid + it * THREADS;        // 0..1535
            int n = s >> 3, j = s & 7;
            *(uint4*)(base + B1_R + n * 144 + j * 16) = bReg[it];
        }
    };

    // ================= stage 1: pipelined, double-buffered, 2 passes =================
    load_chunk(0);
    store_chunk(0);
    load_chunk(1);
    __syncthreads();

    for (int c = 0; c < 8; ++c) {
        if (c < 7) store_chunk((c + 1) & 1);
        if (c < 6) load_chunk(c + 2);

        const uint32_t cb = sb + CHUNK0 + ((c & 1) ? CHUNKSZ : 0);
        const uint32_t aHi = cb + A1HI_R + aoffA;
        const uint32_t aLo = cb + A1LO_R + aoffA;
        const uint32_t bB  = cb + B1_R   + boffB;

        #pragma unroll
        for (int ks = 0; ks < 4; ++ks) {
            const uint32_t ko = ks * 32;
            uint32_t ah[2][4], al[2][4], bf[3][4];
            #pragma unroll
            for (int mi = 0; mi < 2; ++mi) ldsm_x4(aHi + mi * 2304 + ko, ah[mi]);
            #pragma unroll
            for (int p = 0; p < 3; ++p)    ldsm_x4(bB + p * 2304 + ko, bf[p]);
            #pragma unroll
            for (int mi = 0; mi < 2; ++mi)
                #pragma unroll
                for (int ni = 0; ni < 6; ++ni)
                    mma_f16(acc[mi][ni], ah[mi], &bf[ni >> 1][(ni & 1) * 2]);
            #pragma unroll
            for (int mi = 0; mi < 2; ++mi) ldsm_x4(aLo + mi * 2304 + ko, al[mi]);
            #pragma unroll
            for (int mi = 0; mi < 2; ++mi)
                #pragma unroll
                for (int ni = 0; ni < 6; ++ni)
                    mma_f16(acc[mi][ni], al[mi], &bf[ni >> 1][(ni & 1) * 2]);
        }
        __syncthreads();
    }

    // ================= epilogue 1: bias, LN(128), GELU, split -> A2; identity -> idbf ====
    #pragma unroll
    for (int mi = 0; mi < 2; ++mi)
        #pragma unroll
        for (int ni = 0; ni < 6; ++ni) {
            int cc = n0 + ni * 8 + qc;
            float2 bv = (cc < H) ? *(const float2*)(b1 + cc)
                                 : *(const float2*)(bs + cc - H);
            acc[mi][ni][0] += bv.x; acc[mi][ni][1] += bv.y;
            acc[mi][ni][2] += bv.x; acc[mi][ni][3] += bv.y;
        }
    {
        const int nLim = (nw < 2) ? 6 : ((nw == 2) ? 4 : 0);
        float s[4] = {0,0,0,0}, q[4] = {0,0,0,0};
        for (int mi = 0; mi < 2; ++mi)
            for (int ni = 0; ni < nLim; ++ni) {
                s[mi*2+0] += acc[mi][ni][0] + acc[mi][ni][1];
                q[mi*2+0] += acc[mi][ni][0]*acc[mi][ni][0] + acc[mi][ni][1]*acc[mi][ni][1];
                s[mi*2+1] += acc[mi][ni][2] + acc[mi][ni][3];
                q[mi*2+1] += acc[mi][ni][2]*acc[mi][ni][2] + acc[mi][ni][3]*acc[mi][ni][3];
            }
        #pragma unroll
        for (int i = 0; i < 4; ++i) {
            s[i] += __shfl_xor_sync(0xffffffffu, s[i], 1);
            s[i] += __shfl_xor_sync(0xffffffffu, s[i], 2);
            q[i] += __shfl_xor_sync(0xffffffffu, q[i], 1);
            q[i] += __shfl_xor_sync(0xffffffffu, q[i], 2);
        }
        if ((lane & 3) == 0 && nw < 3) {
            #pragma unroll
            for (int i = 0; i < 4; ++i) {
                int r = m0 + qr + ((i & 1) ? 8 : 0) + ((i >> 1) ? 16 : 0);
                psum[r * 4 + nw] = s[i];
                psq [r * 4 + nw] = q[i];
            }
        }
    }
    __syncthreads();
    if (tid < MTILE) {
        float S = psum[tid*4] + psum[tid*4+1] + psum[tid*4+2];
        float Q = psq [tid*4] + psq [tid*4+1] + psq [tid*4+2];
        float mu = S * (1.0f / H);
        mu_s[tid] = mu;
        rs_s[tid] = rsqrtf(Q * (1.0f / H) - mu * mu + 1e-5f);
    }
    __syncthreads();
    {
        int rows[4];
        float muv[4], rsv[4];
        #pragma unroll
        for (int i = 0; i < 4; ++i) {
            rows[i] = m0 + qr + ((i & 1) ? 8 : 0) + ((i >> 1) ? 16 : 0);
            muv[i] = mu_s[rows[i]];
            rsv[i] = rs_s[rows[i]];
        }
        #pragma unroll
        for (int mi = 0; mi < 2; ++mi)
            #pragma unroll
            for (int ni = 0; ni < 6; ++ni) {
                int cc = n0 + ni * 8 + qc;
                if (cc < H) {
                    float2 gv = *(const float2*)(g1 + cc);
                    float2 bev = *(const float2*)(be1 + cc);
                    #pragma unroll
                    for (int half = 0; half < 2; ++half) {
                        int i = mi * 2 + half, r = rows[i];
                        float y0 = (acc[mi][ni][half*2]   - muv[i]) * rsv[i] * gv.x + bev.x;
                        float y1 = (acc[mi][ni][half*2+1] - muv[i]) * rsv[i] * gv.y + bev.y;
                        float h0 = gelu_exact(y0), h1 = gelu_exact(y1);
                        __half hh0,ll0,hh1,ll1;
                        split2h(h0, hh0, ll0); split2h(h1, hh1, ll1);
                        *(uint32_t*)(smem + OFF_A2HI + r * 272 + cc * 2) = pack_h(hh0, hh1);
                        *(uint32_t*)(smem + OFF_A2LO + r * 272 + cc * 2) = pack_h(ll0, ll1);
                    }
                } else {
                    #pragma unroll
                    for (int half = 0; half < 2; ++half) {
                        int i = mi * 2 + half, r = rows[i];
                        *(float2*)(idbf + r * 64 + (cc - H)) =
                            make_float2(acc[mi][ni][half*2], acc[mi][ni][half*2+1]);
                    }
                }
            }
    }

    // --- stage B2: [64][128] hi & lo -> pitch 272 ---
    #pragma unroll
    for (int it = 0; it < 4; ++it) {
        int s = tid + it * THREADS;        // 0..2047 (2 x 1024 slots)
        int buf = (s >= 1024);
        int t2 = s - buf * 1024;
        int n = t2 >> 4, j = t2 & 15;
        const char* srcp = (buf ? (const char*)g_W2T_lo : (const char*)g_W2T_hi)
                           + n * 256 + j * 16;
        *(uint4*)(smem + (buf ? OFF_B2LO : OFF_B2HI) + n * 272 + j * 16) =
            *(const uint4*)srcp;
    }
    __syncthreads();

    // ================= stage 2: [128,128] x [128,64], 3 passes =================
    float ac2[2][2][4];
    #pragma unroll
    for (int mi = 0; mi < 2; ++mi)
        #pragma unroll
        for (int ni = 0; ni < 2; ++ni)
            #pragma unroll
            for (int j = 0; j < 4; ++j) ac2[mi][ni][j] = 0.0f;
    {
        const uint32_t a2Hi = sb + OFF_A2HI + (m0 + lrow) * 272 + kcol * 2;
        const uint32_t a2Lo = sb + OFF_A2LO + (m0 + lrow) * 272 + kcol * 2;
        const uint32_t b2Hi = sb + OFF_B2HI + (nw * 16 + brow) * 272 + bcol * 2;
        const uint32_t b2Lo = sb + OFF_B2LO + (nw * 16 + brow) * 272 + bcol * 2;
        #pragma unroll
        for (int ks = 0; ks < 8; ++ks) {
            const uint32_t ko = ks * 32;
            uint32_t ah[2][4], bh[4], al[2][4], bl[4];
            #pragma unroll
            for (int mi = 0; mi < 2; ++mi) ldsm_x4(a2Hi + mi * 4352 + ko, ah[mi]);
            ldsm_x4(b2Hi + ko, bh);
            #pragma unroll
            for (int mi = 0; mi < 2; ++mi)
                #pragma unroll
                for (int ni = 0; ni < 2; ++ni)
                    mma_f16(ac2[mi][ni], ah[mi], &bh[ni * 2]);
            #pragma unroll
            for (int mi = 0; mi < 2; ++mi) ldsm_x4(a2Lo + mi * 4352 + ko, al[mi]);
            #pragma unroll
            for (int mi = 0; mi < 2; ++mi)
                #pragma unroll
                for (int ni = 0; ni < 2; ++ni)
                    mma_f16(ac2[mi][ni], al[mi], &bh[ni * 2]);
            ldsm_x4(b2Lo + ko, bl);
            #pragma unroll
            for (int mi = 0; mi < 2; ++mi)
                #pragma unroll
                for (int ni = 0; ni < 2; ++ni)
                    mma_f16(ac2[mi][ni], ah[mi], &bl[ni * 2]);
        }
    }
    __syncthreads();

    // ================= epilogue 2: bias, LN(64), +identity, GELU, dot W3 ============
    #pragma unroll
    for (int mi = 0; mi < 2; ++mi)
        #pragma unroll
        for (int ni = 0; ni < 2; ++ni) {
            int cc = nw * 16 + ni * 8 + qc;
            float2 bv = *(const float2*)(b2 + cc);
            ac2[mi][ni][0] += bv.x; ac2[mi][ni][1] += bv.y;
            ac2[mi][ni][2] += bv.x; ac2[mi][ni][3] += bv.y;
        }
    {
        float s[4] = {0,0,0,0}, q[4] = {0,0,0,0};
        #pragma unroll
        for (int mi = 0; mi < 2; ++mi)
            #pragma unroll
            for (int ni = 0; ni < 2; ++ni) {
                s[mi*2+0] += ac2[mi][ni][0] + ac2[mi][ni][1];
                q[mi*2+0] += ac2[mi][ni][0]*ac2[mi][ni][0] + ac2[mi][ni][1]*ac2[mi][ni][1];
                s[mi*2+1] += ac2[mi][ni][2] + ac2[mi][ni][3];
                q[mi*2+1] += ac2[mi][ni][2]*ac2[mi][ni][2] + ac2[mi][ni][3]*ac2[mi][ni][3];
            }
        #pragma unroll
        for (int i = 0; i < 4; ++i) {
            s[i] += __shfl_xor_sync(0xffffffffu, s[i], 1);
            s[i] += __shfl_xor_sync(0xffffffffu, s[i], 2);
            q[i] += __shfl_xor_sync(0xffffffffu, q[i], 1);
            q[i] += __shfl_xor_sync(0xffffffffu, q[i], 2);
        }
        if ((lane & 3) == 0) {
            #pragma unroll
            for (int i = 0; i < 4; ++i) {
                int r = m0 + qr + ((i & 1) ? 8 : 0) + ((i >> 1) ? 16 : 0);
                psum[r * 4 + nw] = s[i];
                psq [r * 4 + nw] = q[i];
            }
        }
    }
    __syncthreads();
    if (tid < MTILE) {
        float S = psum[tid*4] + psum[tid*4+1] + psum[tid*4+2] + psum[tid*4+3];
        float Q = psq [tid*4] + psq [tid*4+1] + psq [tid*4+2] + psq [tid*4+3];
        float mu = S * (1.0f / H2);
        mu_s[tid] = mu;
        rs_s[tid] = rsqrtf(Q * (1.0f / H2) - mu * mu + 1e-5f);
    }
    __syncthreads();
    {
        int rows[4];
        float muv[4], rsv[4], dotp[4] = {0,0,0,0};
        #pragma unroll
        for (int i = 0; i < 4; ++i) {
            rows[i] = m0 + qr + ((i & 1) ? 8 : 0) + ((i >> 1) ? 16 : 0);
            muv[i] = mu_s[rows[i]];
            rsv[i] = rs_s[rows[i]];
        }
        #pragma unroll
        for (int mi = 0; mi < 2; ++mi)
            #pragma unroll
            for (int ni = 0; ni < 2; ++ni) {
                int cc = nw * 16 + ni * 8 + qc;
                float2 gv = *(const float2*)(g2 + cc);
                float2 bev = *(const float2*)(be2 + cc);
                float2 wv = *(const float2*)(W3 + cc);
                #pragma unroll
                for (int half = 0; half < 2; ++half) {
                    int i = mi * 2 + half, r = rows[i];
                    float2 idv = *(const float2*)(idbf + r * 64 + cc);
                    float y0 = (ac2[mi][ni][half*2]   - muv[i]) * rsv[i] * gv.x + bev.x;
                    float y1 = (ac2[mi][ni][half*2+1] - muv[i]) * rsv[i] * gv.y + bev.y;
                    float h0 = gelu_exact(y0 + idv.x);
                    float h1 = gelu_exact(y1 + idv.y);
                    dotp[i] += h0 * wv.x + h1 * wv.y;
                }
            }
        #pragma unroll
        for (int i = 0; i < 4; ++i) {
            dotp[i] += __shfl_xor_sync(0xffffffffu, dotp[i], 1);
            dotp[i] += __shfl_xor_sync(0xffffffffu, dotp[i], 2);
        }
        __syncthreads();
        if ((lane & 3) == 0) {
            #pragma unroll
            for (int i = 0; i < 4; ++i)
                psum[rows[i] * 4 + nw] = dotp[i];
        }
    }
    __syncthreads();
    if (tid < MTILE && (e0 + tid) < E) {
        out[e0 + tid] = psum[tid*4] + psum[tid*4+1] + psum[tid*4+2] + psum[tid*4+3]
                        + b3[0];
    }
}

extern "C" void kernel_launch(void* const* d_in, const int* in_sizes, int n_in,
                              void* d_out, int out_size) {
    const float* drug = (const float*)d_in[0];
    const float* dis  = (const float*)d_in[1];
    const int*   src  = (const int*)  d_in[2];
    const int*   dst  = (const int*)  d_in[3];
    const float* W1   = (const float*)d_in[4];
    const float* b1   = (const float*)d_in[5];
    const float* g1   = (const float*)d_in[6];
    const float* be1  = (const float*)d_in[7];
    const float* W2   = (const float*)d_in[8];
    const float* b2   = (const float*)d_in[9];
    const float* g2   = (const float*)d_in[10];
    const float* be2  = (const float*)d_in[11];
    const float* W3   = (const float*)d_in[12];
    const float* b3   = (const float*)d_in[13];
    const float* Ws   = (const float*)d_in[14];
    const float* bs   = (const float*)d_in[15];
    const int E = in_sizes[2];

    prep_weights<<<(NC1 * KDIM + H2 * H + 255) / 256, 256>>>(W1, Ws, W2);

    cudaFuncSetAttribute(mlp_hmma_kernel,
                         cudaFuncAttributeMaxDynamicSharedMemorySize, SMEM_BYTES);
    const int grid = (E + MTILE - 1) / MTILE;
    mlp_hmma_kernel<<<grid, THREADS, SMEM_BYTES>>>(
        drug, dis, src, dst, b1, g1, be1, b2, g2, be2, W3, b3, bs,
        (float*)d_out, E);
}

// round 17
// speedup vs baseline: 1.0025x; 1.0025x over previous
#include <cuda_runtime.h>
#include <cuda_fp16.h>
#include <math.h>
#include <stdint.h>

// ---------------- problem dims ----------------
#define DFEAT 256
#define KDIM  512
#define H     128
#define H2    64
#define NC1   192          // fused stage-1 output cols (W1 | Ws)
#define MTILE 128          // edges per CTA
#define KC    64           // K-chunk
#define THREADS 512        // 16 warps: 4 m-warps x 4 n-warps

// ---------------- smem layout (bytes) ----------------
#define OFF_PS   0          // [128][4] float row partial sums
#define OFF_PQ   2048
#define OFF_MU   4096
#define OFF_RS   4608
#define OFF_RIDX 5120       // int[256]
// double-buffered stage-1 chunk sets (row pitch 144B = 64 fp16 + 16B pad)
#define CHUNK0   6144
#define A1HI_R   0          // 128*144 = 18432
#define A1LO_R   18432
#define B1_R     36864      // 192*144 = 27648
#define CHUNKSZ  64512
// phase 2 (aliases chunk buffers; pitch 272B = 128 fp16 + 16B pad)
#define OFF_A2HI 6144       // 128*272 = 34816
#define OFF_A2LO 40960
#define OFF_B2HI 75776      // 64*272 = 17408
#define OFF_B2LO 93184
#define OFF_ID   110592     // [128][64] float identity (ends 143360)
#define SMEM_BYTES 143360

// ---------------- prepped weights ----------------
__device__ __align__(16) __half g_WcatT[NC1 * KDIM];   // [n][k] fp16 (single)
__device__ __align__(16) __half g_W2T_hi[H2 * H];      // [n][k]
__device__ __align__(16) __half g_W2T_lo[H2 * H];

// ---------------- helpers ----------------
__device__ __forceinline__ uint32_t smem_u32(const void* p) {
    uint32_t a;
    asm("{ .reg .u64 t; cvta.to.shared.u64 t, %1; cvt.u32.u64 %0, t; }" : "=r"(a) : "l"(p));
    return a;
}
__device__ __forceinline__ void ldsm_x4(uint32_t addr, uint32_t* r) {
    asm volatile("ldmatrix.sync.aligned.m8n8.x4.shared.b16 {%0,%1,%2,%3}, [%4];"
        : "=r"(r[0]), "=r"(r[1]), "=r"(r[2]), "=r"(r[3]) : "r"(addr));
}
__device__ __forceinline__ void mma_f16(float* d, const uint32_t* a, const uint32_t* b) {
    asm volatile(
        "mma.sync.aligned.m16n8k16.row.col.f32.f16.f16.f32 "
        "{%0,%1,%2,%3}, {%4,%5,%6,%7}, {%8,%9}, {%0,%1,%2,%3};"
        : "+f"(d[0]), "+f"(d[1]), "+f"(d[2]), "+f"(d[3])
        : "r"(a[0]), "r"(a[1]), "r"(a[2]), "r"(a[3]), "r"(b[0]), "r"(b[1]));
}
__device__ __forceinline__ uint32_t pack_h(__half a, __half b) {
    return (uint32_t)__half_as_ushort(a) | ((uint32_t)__half_as_ushort(b) << 16);
}
__device__ __forceinline__ void split2h(float f, __half& h, __half& l) {
    h = __float2half_rn(f);
    l = __float2half_rn(f - __half2float(h));
}
__device__ __forceinline__ float gelu_exact(float x) {
    return 0.5f * x * (1.0f + erff(x * 0.70710678118654752440f));
}

// ---------------- prep kernel: convert/split + transpose weights ----------------
__global__ void prep_weights(const float* __restrict__ W1, const float* __restrict__ Ws,
                             const float* __restrict__ W2) {
    int i = blockIdx.x * 256 + threadIdx.x;
    if (i < NC1 * KDIM) {
        int n = i / KDIM, k = i % KDIM;
        float w = (n < H) ? W1[k * H + n] : Ws[k * H2 + (n - H)];
        g_WcatT[i] = __float2half_rn(w);
    } else {
        int j = i - NC1 * KDIM;
        if (j < H2 * H) {
            int n = j / H, k = j % H;
            float w = W2[k * H2 + n];
            __half h, l; split2h(w, h, l);
            g_W2T_hi[j] = h; g_W2T_lo[j] = l;
        }
    }
}

// ---------------- main kernel ----------------
__global__ void __launch_bounds__(THREADS, 1)
mlp_hmma_kernel(const float* __restrict__ drug, const float* __restrict__ dis,
                const int* __restrict__ src, const int* __restrict__ dst,
                const float* __restrict__ b1, const float* __restrict__ g1,
                const float* __restrict__ be1,
                const float* __restrict__ b2, const float* __restrict__ g2,
                const float* __restrict__ be2,
                const float* __restrict__ W3, const float* __restrict__ b3,
                const float* __restrict__ bs,
                float* __restrict__ out, int E)
{
    extern __shared__ char smem[];
    const uint32_t sb = smem_u32(smem);
    const int tid = threadIdx.x, wid = tid >> 5, lane = tid & 31;
    const int e0 = blockIdx.x * MTILE;

    float* psum = (float*)(smem + OFF_PS);
    float* psq  = (float*)(smem + OFF_PQ);
    float* mu_s = (float*)(smem + OFF_MU);
    float* rs_s = (float*)(smem + OFF_RS);
    int*   ridx = (int*)(smem + OFF_RIDX);
    float* idbf = (float*)(smem + OFF_ID);

    if (tid < MTILE) {
        int e = e0 + tid;
        ridx[tid]         = (e < E) ? src[e] : 0;
        ridx[MTILE + tid] = (e < E) ? dst[e] : 0;
    }
    __syncthreads();

    // warp tiling
    const int mw = wid >> 2, nw = wid & 3;
    const int m0 = mw * 32;
    const int n0 = nw * 48;
    const int lrow = lane & 15;
    const int kcol = (lane >> 4) * 8;
    const int brow = (lane & 7) + ((lane >> 4) * 8);
    const int bcol = ((lane >> 3) & 1) * 8;
    const int qr = lane >> 2;
    const int qc = (lane & 3) * 2;

    const uint32_t aoffA = (m0 + lrow) * 144 + kcol * 2;
    const uint32_t boffB = (n0 + brow) * 144 + bcol * 2;

    // staging coords
    const int grow = tid >> 2, gq = tid & 3;   // A gather: 128 rows x 4 thr

    float acc[2][6][4];
    #pragma unroll
    for (int mi = 0; mi < 2; ++mi)
        #pragma unroll
        for (int ni = 0; ni < 6; ++ni)
            #pragma unroll
            for (int j = 0; j < 4; ++j) acc[mi][ni][j] = 0.0f;

    float4 aReg[4];
    uint4  bReg[3];

    // ---- prefetch helpers ----
    auto load_chunk = [&](int cc) {
        const float* tab = (cc < 4) ? drug : dis;
        const long idx = (long)ridx[((cc < 4) ? 0 : MTILE) + grow];
        const float* sp = tab + idx * DFEAT + (cc & 3) * KC + gq * 16;
        #pragma unroll
        for (int j = 0; j < 4; ++j) aReg[j] = *(const float4*)(sp + 4 * j);
        // B tile: 192 rows x 8 uint4 slots = 1536 slots = exactly 3 iterations
        #pragma unroll
        for (int it = 0; it < 3; ++it) {
            int s = tid + it * THREADS;        // 0..1535
            int n = s >> 3, j = s & 7;
            bReg[it] = *(const uint4*)((const char*)g_WcatT + n * 1024 + cc * 128 + j * 16);
        }
    };
    auto store_chunk = [&](int bsel) {
        char* base = smem + CHUNK0 + bsel * CHUNKSZ;
        char* dh = base + A1HI_R + grow * 144 + gq * 32;
        char* dl = base + A1LO_R + grow * 144 + gq * 32;
        #pragma unroll
        for (int j = 0; j < 4; ++j) {
            __half h0,h1,h2,h3,l0,l1,l2,l3;
            split2h(aReg[j].x, h0, l0); split2h(aReg[j].y, h1, l1);
            split2h(aReg[j].z, h2, l2); split2h(aReg[j].w, h3, l3);
            *(uint2*)(dh + j * 8) = make_uint2(pack_h(h0,h1), pack_h(h2,h3));
            *(uint2*)(dl + j * 8) = make_uint2(pack_h(l0,l1), pack_h(l2,l3));
        }
        #pragma unroll
        for (int it = 0; it < 3; ++it) {
            int s = tid + it * THREADS;        // 0..1535
            int n = s >> 3, j = s & 7;
            *(uint4*)(base + B1_R + n * 144 + j * 16) = bReg[it];
        }
    };

    // ================= stage 1: pipelined, double-buffered, 2 passes =================
    load_chunk(0);
    store_chunk(0);
    load_chunk(1);
    __syncthreads();

    for (int c = 0; c < 8; ++c) {
        if (c < 7) store_chunk((c + 1) & 1);
        if (c < 6) load_chunk(c + 2);

        const uint32_t cb = sb + CHUNK0 + ((c & 1) ? CHUNKSZ : 0);
        const uint32_t aHi = cb + A1HI_R + aoffA;
        const uint32_t aLo = cb + A1LO_R + aoffA;
        const uint32_t bB  = cb + B1_R   + boffB;

        #pragma unroll
        for (int ks = 0; ks < 4; ++ks) {
            const uint32_t ko = ks * 32;
            uint32_t ah[2][4], al[2][4], bf[3][4];
            #pragma unroll
            for (int mi = 0; mi < 2; ++mi) ldsm_x4(aHi + mi * 2304 + ko, ah[mi]);
            #pragma unroll
            for (int p = 0; p < 3; ++p)    ldsm_x4(bB + p * 2304 + ko, bf[p]);
            #pragma unroll
            for (int mi = 0; mi < 2; ++mi)
                #pragma unroll
                for (int ni = 0; ni < 6; ++ni)
                    mma_f16(acc[mi][ni], ah[mi], &bf[ni >> 1][(ni & 1) * 2]);
            #pragma unroll
            for (int mi = 0; mi < 2; ++mi) ldsm_x4(aLo + mi * 2304 + ko, al[mi]);
            #pragma unroll
            for (int mi = 0; mi < 2; ++mi)
                #pragma unroll
                for (int ni = 0; ni < 6; ++ni)
                    mma_f16(acc[mi][ni], al[mi], &bf[ni >> 1][(ni & 1) * 2]);
        }
        __syncthreads();
    }

    // ================= epilogue 1: bias, LN(128), GELU, split -> A2; identity -> idbf ====
    #pragma unroll
    for (int mi = 0; mi < 2; ++mi)
        #pragma unroll
        for (int ni = 0; ni < 6; ++ni) {
            int cc = n0 + ni * 8 + qc;
            float2 bv = (cc < H) ? *(const float2*)(b1 + cc)
                                 : *(const float2*)(bs + cc - H);
            acc[mi][ni][0] += bv.x; acc[mi][ni][1] += bv.y;
            acc[mi][ni][2] += bv.x; acc[mi][ni][3] += bv.y;
        }
    {
        const int nLim = (nw < 2) ? 6 : ((nw == 2) ? 4 : 0);
        float s[4] = {0,0,0,0}, q[4] = {0,0,0,0};
        for (int mi = 0; mi < 2; ++mi)
            for (int ni = 0; ni < nLim; ++ni) {
                s[mi*2+0] += acc[mi][ni][0] + acc[mi][ni][1];
                q[mi*2+0] += acc[mi][ni][0]*acc[mi][ni][0] + acc[mi][ni][1]*acc[mi][ni][1];
                s[mi*2+1] += acc[mi][ni][2] + acc[mi][ni][3];
                q[mi*2+1] += acc[mi][ni][2]*acc[mi][ni][2] + acc[mi][ni][3]*acc[mi][ni][3];
            }
        #pragma unroll
        for (int i = 0; i < 4; ++i) {
            s[i] += __shfl_xor_sync(0xffffffffu, s[i], 1);
            s[i] += __shfl_xor_sync(0xffffffffu, s[i], 2);
            q[i] += __shfl_xor_sync(0xffffffffu, q[i], 1);
            q[i] += __shfl_xor_sync(0xffffffffu, q[i], 2);
        }
        if ((lane & 3) == 0 && nw < 3) {
            #pragma unroll
            for (int i = 0; i < 4; ++i) {
                int r = m0 + qr + ((i & 1) ? 8 : 0) + ((i >> 1) ? 16 : 0);
                psum[r * 4 + nw] = s[i];
                psq [r * 4 + nw] = q[i];
            }
        }
    }
    __syncthreads();
    if (tid < MTILE) {
        float S = psum[tid*4] + psum[tid*4+1] + psum[tid*4+2];
        float Q = psq [tid*4] + psq [tid*4+1] + psq [tid*4+2];
        float mu = S * (1.0f / H);
        mu_s[tid] = mu;
        rs_s[tid] = rsqrtf(Q * (1.0f / H) - mu * mu + 1e-5f);
    }
    __syncthreads();
    {
        int rows[4];
        float muv[4], rsv[4];
        #pragma unroll
        for (int i = 0; i < 4; ++i) {
            rows[i] = m0 + qr + ((i & 1) ? 8 : 0) + ((i >> 1) ? 16 : 0);
            muv[i] = mu_s[rows[i]];
            rsv[i] = rs_s[rows[i]];
        }
        #pragma unroll
        for (int mi = 0; mi < 2; ++mi)
            #pragma unroll
            for (int ni = 0; ni < 6; ++ni) {
                int cc = n0 + ni * 8 + qc;
                if (cc < H) {
                    float2 gv = *(const float2*)(g1 + cc);
                    float2 bev = *(const float2*)(be1 + cc);
                    #pragma unroll
                    for (int half = 0; half < 2; ++half) {
                        int i = mi * 2 + half, r = rows[i];
                        float y0 = (acc[mi][ni][half*2]   - muv[i]) * rsv[i] * gv.x + bev.x;
                        float y1 = (acc[mi][ni][half*2+1] - muv[i]) * rsv[i] * gv.y + bev.y;
                        float h0 = gelu_exact(y0), h1 = gelu_exact(y1);
                        __half hh0,ll0,hh1,ll1;
                        split2h(h0, hh0, ll0); split2h(h1, hh1, ll1);
                        *(uint32_t*)(smem + OFF_A2HI + r * 272 + cc * 2) = pack_h(hh0, hh1);
                        *(uint32_t*)(smem + OFF_A2LO + r * 272 + cc * 2) = pack_h(ll0, ll1);
                    }
                } else {
                    #pragma unroll
                    for (int half = 0; half < 2; ++half) {
                        int i = mi * 2 + half, r = rows[i];
                        *(float2*)(idbf + r * 64 + (cc - H)) =
                            make_float2(acc[mi][ni][half*2], acc[mi][ni][half*2+1]);
                    }
                }
            }
    }

    // --- stage B2: [64][128] hi & lo -> pitch 272 ---
    #pragma unroll
    for (int it = 0; it < 4; ++it) {
        int s = tid + it * THREADS;        // 0..2047 (2 x 1024 slots)
        int buf = (s >= 1024);
        int t2 = s - buf * 1024;
        int n = t2 >> 4, j = t2 & 15;
        const char* srcp = (buf ? (const char*)g_W2T_lo : (const char*)g_W2T_hi)
                           + n * 256 + j * 16;
        *(uint4*)(smem + (buf ? OFF_B2LO : OFF_B2HI) + n * 272 + j * 16) =
            *(const uint4*)srcp;
    }
    __syncthreads();

    // ================= stage 2: [128,128] x [128,64], 3 passes =================
    float ac2[2][2][4];
    #pragma unroll
    for (int mi = 0; mi < 2; ++mi)
        #pragma unroll
        for (int ni = 0; ni < 2; ++ni)
            #pragma unroll
            for (int j = 0; j < 4; ++j) ac2[mi][ni][j] = 0.0f;
    {
        const uint32_t a2Hi = sb + OFF_A2HI + (m0 + lrow) * 272 + kcol * 2;
        const uint32_t a2Lo = sb + OFF_A2LO + (m0 + lrow) * 272 + kcol * 2;
        const uint32_t b2Hi = sb + OFF_B2HI + (nw * 16 + brow) * 272 + bcol * 2;
        const uint32_t b2Lo = sb + OFF_B2LO + (nw * 16 + brow) * 272 + bcol * 2;
        #pragma unroll
        for (int ks = 0; ks < 8; ++ks) {
            const uint32_t ko = ks * 32;
            uint32_t ah[2][4], bh[4], al[2][4], bl[4];
            #pragma unroll
            for (int mi = 0; mi < 2; ++mi) ldsm_x4(a2Hi + mi * 4352 + ko, ah[mi]);
            ldsm_x4(b2Hi + ko, bh);
            #pragma unroll
            for (int mi = 0; mi < 2; ++mi)
                #pragma unroll
                for (int ni = 0; ni < 2; ++ni)
                    mma_f16(ac2[mi][ni], ah[mi], &bh[ni * 2]);
            #pragma unroll
            for (int mi = 0; mi < 2; ++mi) ldsm_x4(a2Lo + mi * 4352 + ko, al[mi]);
            #pragma unroll
            for (int mi = 0; mi < 2; ++mi)
                #pragma unroll
                for (int ni = 0; ni < 2; ++ni)
                    mma_f16(ac2[mi][ni], al[mi], &bh[ni * 2]);
            ldsm_x4(b2Lo + ko, bl);
            #pragma unroll
            for (int mi = 0; mi < 2; ++mi)
                #pragma unroll
                for (int ni = 0; ni < 2; ++ni)
                    mma_f16(ac2[mi][ni], ah[mi], &bl[ni * 2]);
        }
    }
    __syncthreads();

    // ================= epilogue 2: bias, LN(64), +identity, GELU, dot W3 ============
    #pragma unroll
    for (int mi = 0; mi < 2; ++mi)
        #pragma unroll
        for (int ni = 0; ni < 2; ++ni) {
            int cc = nw * 16 + ni * 8 + qc;
            float2 bv = *(const float2*)(b2 + cc);
            ac2[mi][ni][0] += bv.x; ac2[mi][ni][1] += bv.y;
            ac2[mi][ni][2] += bv.x; ac2[mi][ni][3] += bv.y;
        }
    {
        float s[4] = {0,0,0,0}, q[4] = {0,0,0,0};
        #pragma unroll
        for (int mi = 0; mi < 2; ++mi)
            #pragma unroll
            for (int ni = 0; ni < 2; ++ni) {
                s[mi*2+0] += ac2[mi][ni][0] + ac2[mi][ni][1];
                q[mi*2+0] += ac2[mi][ni][0]*ac2[mi][ni][0] + ac2[mi][ni][1]*ac2[mi][ni][1];
                s[mi*2+1] += ac2[mi][ni][2] + ac2[mi][ni][3];
                q[mi*2+1] += ac2[mi][ni][2]*ac2[mi][ni][2] + ac2[mi][ni][3]*ac2[mi][ni][3];
            }
        #pragma unroll
        for (int i = 0; i < 4; ++i) {
            s[i] += __shfl_xor_sync(0xffffffffu, s[i], 1);
            s[i] += __shfl_xor_sync(0xffffffffu, s[i], 2);
            q[i] += __shfl_xor_sync(0xffffffffu, q[i], 1);
            q[i] += __shfl_xor_sync(0xffffffffu, q[i], 2);
        }
        if ((lane & 3) == 0) {
            #pragma unroll
            for (int i = 0; i < 4; ++i) {
                int r = m0 + qr + ((i & 1) ? 8 : 0) + ((i >> 1) ? 16 : 0);
                psum[r * 4 + nw] = s[i];
                psq [r * 4 + nw] = q[i];
            }
        }
    }
    __syncthreads();
    if (tid < MTILE) {
        float S = psum[tid*4] + psum[tid*4+1] + psum[tid*4+2] + psum[tid*4+3];
        float Q = psq [tid*4] + psq [tid*4+1] + psq [tid*4+2] + psq [tid*4+3];
        float mu = S * (1.0f / H2);
        mu_s[tid] = mu;
        rs_s[tid] = rsqrtf(Q * (1.0f / H2) - mu * mu + 1e-5f);
    }
    __syncthreads();
    {
        int rows[4];
        float muv[4], rsv[4], dotp[4] = {0,0,0,0};
        #pragma unroll
        for (int i = 0; i < 4; ++i) {
            rows[i] = m0 + qr + ((i & 1) ? 8 : 0) + ((i >> 1) ? 16 : 0);
            muv[i] = mu_s[rows[i]];
            rsv[i] = rs_s[rows[i]];
        }
        #pragma unroll
        for (int mi = 0; mi < 2; ++mi)
            #pragma unroll
            for (int ni = 0; ni < 2; ++ni) {
                int cc = nw * 16 + ni * 8 + qc;
                float2 gv = *(const float2*)(g2 + cc);
                float2 bev = *(const float2*)(be2 + cc);
                float2 wv = *(const float2*)(W3 + cc);
                #pragma unroll
                for (int half = 0; half < 2; ++half) {
                    int i = mi * 2 + half, r = rows[i];
                    float2 idv = *(const float2*)(idbf + r * 64 + cc);
                    float y0 = (ac2[mi][ni][half*2]   - muv[i]) * rsv[i] * gv.x + bev.x;
                    float y1 = (ac2[mi][ni][half*2+1] - muv[i]) * rsv[i] * gv.y + bev.y;
                    float h0 = gelu_exact(y0 + idv.x);
                    float h1 = gelu_exact(y1 + idv.y);
                    dotp[i] += h0 * wv.x + h1 * wv.y;
                }
            }
        #pragma unroll
        for (int i = 0; i < 4; ++i) {
            dotp[i] += __shfl_xor_sync(0xffffffffu, dotp[i], 1);
            dotp[i] += __shfl_xor_sync(0xffffffffu, dotp[i], 2);
        }
        __syncthreads();
        if ((lane & 3) == 0) {
            #pragma unroll
            for (int i = 0; i < 4; ++i)
                psum[rows[i] * 4 + nw] = dotp[i];
        }
    }
    __syncthreads();
    if (tid < MTILE && (e0 + tid) < E) {
        out[e0 + tid] = psum[tid*4] + psum[tid*4+1] + psum[tid*4+2] + psum[tid*4+3]
                        + b3[0];
    }
}

extern "C" void kernel_launch(void* const* d_in, const int* in_sizes, int n_in,
                              void* d_out, int out_size) {
    const float* drug = (const float*)d_in[0];
    const float* dis  = (const float*)d_in[1];
    const int*   src  = (const int*)  d_in[2];
    const int*   dst  = (const int*)  d_in[3];
    const float* W1   = (const float*)d_in[4];
    const float* b1   = (const float*)d_in[5];
    const float* g1   = (const float*)d_in[6];
    const float* be1  = (const float*)d_in[7];
    const float* W2   = (const float*)d_in[8];
    const float* b2   = (const float*)d_in[9];
    const float* g2   = (const float*)d_in[10];
    const float* be2  = (const float*)d_in[11];
    const float* W3   = (const float*)d_in[12];
    const float* b3   = (const float*)d_in[13];
    const float* Ws   = (const float*)d_in[14];
    const float* bs   = (const float*)d_in[15];
    const int E = in_sizes[2];

    prep_weights<<<(NC1 * KDIM + H2 * H + 255) / 256, 256>>>(W1, Ws, W2);

    cudaFuncSetAttribute(mlp_hmma_kernel,
                         cudaFuncAttributeMaxDynamicSharedMemorySize, SMEM_BYTES);
    const int grid = (E + MTILE - 1) / MTILE;
    mlp_hmma_kernel<<<grid, THREADS, SMEM_BYTES>>>(
        drug, dis, src, dst, b1, g1, be1, b2, g2, be2, W3, b3, bs,
        (float*)d_out, E);
}